// round 6
// baseline (speedup 1.0000x reference)
#include <cuda_runtime.h>
#include <cuda_bf16.h>
#include <cstdint>

#define N_NODES 10000
#define N_EDGES 80000
#define IN_DIM  1024
#define HID     4096
#define OUT_DIM 256

// ---------------- scratch (device globals; no allocations allowed) ----------
__device__ int   g_deg[N_NODES];
__device__ int   g_pos[N_NODES];
__device__ int   g_off[N_NODES + 1];
__device__ int   g_srcs[N_EDGES];
__device__ float g_mean1[(size_t)N_NODES * IN_DIM];     // 40 MB (tf32-rounded)
__device__ float g_xt[(size_t)N_NODES * IN_DIM];        // 40 MB (tf32-rounded x)
__device__ float g_h[(size_t)N_NODES * HID];            // 160 MB (tf32-rounded)
__device__ float g_pl[(size_t)N_NODES * OUT_DIM];       // 10 MB
__device__ float g_pr[(size_t)N_NODES * OUT_DIM];       // 10 MB
__device__ float g_w1l[(size_t)HID * IN_DIM];           // 16 MB (tf32-rounded)
__device__ float g_w1r[(size_t)HID * IN_DIM];           // 16 MB
__device__ float g_w2l[(size_t)OUT_DIM * HID];          // 4 MB
__device__ float g_w2r[(size_t)OUT_DIM * HID];          // 4 MB

// ---------------- helpers ----------------------------------------------------
__device__ __forceinline__ uint32_t f2tf32(float f) {
    uint32_t r;
    asm("cvt.rna.tf32.f32 %0, %1;" : "=r"(r) : "f"(f));
    return r;
}

__device__ __forceinline__ void mma_tf32_16x8x8(float* c, const uint32_t* a, const uint32_t* b) {
    asm volatile(
        "mma.sync.aligned.m16n8k8.row.col.f32.tf32.tf32.f32 "
        "{%0,%1,%2,%3},{%4,%5,%6,%7},{%8,%9},{%0,%1,%2,%3};"
        : "+f"(c[0]), "+f"(c[1]), "+f"(c[2]), "+f"(c[3])
        : "r"(a[0]), "r"(a[1]), "r"(a[2]), "r"(a[3]), "r"(b[0]), "r"(b[1]));
}

__device__ __forceinline__ void cp_async16(uint32_t smem_addr, const void* gptr, int src_bytes) {
    asm volatile("cp.async.cg.shared.global [%0], [%1], 16, %2;\n"
                 :: "r"(smem_addr), "l"(gptr), "r"(src_bytes));
}
__device__ __forceinline__ void cp_commit() {
    asm volatile("cp.async.commit_group;\n" ::: "memory");
}
template <int N>
__device__ __forceinline__ void cp_wait() {
    asm volatile("cp.async.wait_group %0;\n" :: "n"(N) : "memory");
}

// ---------------- elementwise tf32 pre-round ---------------------------------
__global__ void k_cvt_tf32(const float* __restrict__ in, float* __restrict__ outp, int n4) {
    int i = blockIdx.x * blockDim.x + threadIdx.x;
    if (i < n4) {
        float4 v = ((const float4*)in)[i];
        float4 o;
        o.x = __uint_as_float(f2tf32(v.x));
        o.y = __uint_as_float(f2tf32(v.y));
        o.z = __uint_as_float(f2tf32(v.z));
        o.w = __uint_as_float(f2tf32(v.w));
        ((float4*)outp)[i] = o;
    }
}

// ---------------- CSR build --------------------------------------------------
__global__ void k_zero() {
    int i = blockIdx.x * blockDim.x + threadIdx.x;
    if (i < N_NODES) { g_deg[i] = 0; g_pos[i] = 0; }
}

__global__ void k_count(const int* __restrict__ dst) {
    int e = blockIdx.x * blockDim.x + threadIdx.x;
    if (e < N_EDGES) atomicAdd(&g_deg[dst[e]], 1);
}

__global__ void k_scan() {
    __shared__ int s[1024];
    int tid = threadIdx.x;
    int carry = 0;
    if (tid == 0) g_off[0] = 0;
    for (int base = 0; base < N_NODES; base += 1024) {
        int i = base + tid;
        int v = (i < N_NODES) ? g_deg[i] : 0;
        s[tid] = v;
        __syncthreads();
        #pragma unroll
        for (int off = 1; off < 1024; off <<= 1) {
            int t = (tid >= off) ? s[tid - off] : 0;
            __syncthreads();
            s[tid] += t;
            __syncthreads();
        }
        if (i < N_NODES) g_off[i + 1] = carry + s[tid];
        carry += s[1023];
        __syncthreads();
    }
}

__global__ void k_fill(const int* __restrict__ src, const int* __restrict__ dst) {
    int e = blockIdx.x * blockDim.x + threadIdx.x;
    if (e < N_EDGES) {
        int d = dst[e];
        int p = atomicAdd(&g_pos[d], 1);
        g_srcs[g_off[d] + p] = src[e];
    }
}

// deterministic ordering within each segment (avg degree 8 -> trivial cost)
__global__ void k_sort() {
    int n = blockIdx.x * blockDim.x + threadIdx.x;
    if (n >= N_NODES) return;
    int b = g_off[n], e = g_off[n + 1];
    for (int i = b + 1; i < e; ++i) {
        int key = g_srcs[i];
        int j = i - 1;
        while (j >= b && g_srcs[j] > key) { g_srcs[j + 1] = g_srcs[j]; --j; }
        g_srcs[j + 1] = key;
    }
}

// ---------------- mean aggregation (layer 1): one block per node -------------
// Emits tf32-rounded output (consumed only as GEMM A operand).
template <int D, int VEC>
__global__ void k_agg_mean(const float* __restrict__ feat, float* __restrict__ outm) {
    int node = blockIdx.x;
    int beg = g_off[node], end = g_off[node + 1];
    float inv = (end > beg) ? 1.0f / (float)(end - beg) : 0.0f;

    float4 acc[VEC];
    #pragma unroll
    for (int v = 0; v < VEC; ++v) acc[v] = make_float4(0.f, 0.f, 0.f, 0.f);

    for (int e = beg; e < end; ++e) {
        int s = g_srcs[e];
        const float4* row = (const float4*)(feat + (size_t)s * D);
        #pragma unroll
        for (int v = 0; v < VEC; ++v) {
            float4 f = row[threadIdx.x + v * 256];
            acc[v].x += f.x; acc[v].y += f.y; acc[v].z += f.z; acc[v].w += f.w;
        }
    }
    float4* orow = (float4*)(outm + (size_t)node * D);
    #pragma unroll
    for (int v = 0; v < VEC; ++v) {
        float4 o;
        o.x = __uint_as_float(f2tf32(acc[v].x * inv));
        o.y = __uint_as_float(f2tf32(acc[v].y * inv));
        o.z = __uint_as_float(f2tf32(acc[v].z * inv));
        o.w = __uint_as_float(f2tf32(acc[v].w * inv));
        orow[threadIdx.x + v * 256] = o;
    }
}

// ---------------- dual-source fused GEMM (cp.async double-buffered) ----------
// All inputs pre-rounded to tf32 bit patterns -> fragment loads are raw LDS.
// C = A1*B1^T + A2*B2^T + bias; RELU then CVT_OUT (round output to tf32 bits).
template <int BM, int BN, bool RELU, bool CVT_OUT>
__global__ __launch_bounds__(256) void k_gemm_dual(
    const float* __restrict__ A1, const float* __restrict__ B1, int K1,
    const float* __restrict__ A2, const float* __restrict__ B2, int K2,
    const float* __restrict__ bias, float* __restrict__ C,
    int Mrows, int Ncols)
{
    constexpr int BK = 32;
    constexpr int WARPS_M = 4, WARPS_N = 2;
    constexpr int WTM = BM / WARPS_M;
    constexpr int WTN = BN / WARPS_N;
    constexpr int MT = WTM / 16;
    constexpr int NT = WTN / 8;
    constexpr int LDS = BK + 4;
    constexpr int APT = (BM * BK / 4) / 256;
    constexpr int BPT = (BN * BK / 4) / 256;
    constexpr int STAGE = (BM + BN) * LDS;

    extern __shared__ float sm[];
    const uint32_t sm_u32 = (uint32_t)__cvta_generic_to_shared(sm);

    const int tid    = threadIdx.x;
    const int warp   = tid >> 5;
    const int lane   = tid & 31;
    const int g      = lane >> 2;
    const int tig    = lane & 3;
    const int wm0    = (warp / WARPS_N) * WTM;
    const int wn0    = (warp % WARPS_N) * WTN;
    const int mBase  = blockIdx.y * BM;
    const int nBase  = blockIdx.x * BN;

    const int KT1 = K1 / BK;
    const int KT  = KT1 + K2 / BK;

    float c[MT][NT][4];
    #pragma unroll
    for (int mt = 0; mt < MT; ++mt)
        #pragma unroll
        for (int nt = 0; nt < NT; ++nt)
            #pragma unroll
            for (int i = 0; i < 4; ++i) c[mt][nt][i] = 0.f;

    auto issue_tile = [&](int kt, int s) {
        const float* A; const float* B; int K; int ktp;
        if (kt < KT1) { A = A1; B = B1; K = K1; ktp = kt; }
        else          { A = A2; B = B2; K = K2; ktp = kt - KT1; }
        const uint32_t aBase = sm_u32 + (s * STAGE) * 4;
        const uint32_t bBase = aBase + (BM * LDS) * 4;
        #pragma unroll
        for (int p = 0; p < APT; ++p) {
            int l    = tid + p * 256;
            int r    = l >> 3;
            int c4   = (l & 7) * 4;
            int grow = mBase + r;
            int ok   = (grow < Mrows);
            const float* srcp = A + (size_t)(ok ? grow : 0) * K + ktp * BK + c4;
            cp_async16(aBase + (r * LDS + c4) * 4, srcp, ok ? 16 : 0);
        }
        #pragma unroll
        for (int p = 0; p < BPT; ++p) {
            int l    = tid + p * 256;
            int r    = l >> 3;
            int c4   = (l & 7) * 4;
            int grow = nBase + r;
            cp_async16(bBase + (r * LDS + c4) * 4, B + (size_t)grow * K + ktp * BK + c4, 16);
        }
        cp_commit();
    };

    issue_tile(0, 0);

    #pragma unroll 1
    for (int kt = 0; kt < KT; ++kt) {
        const int s = kt & 1;
        if (kt + 1 < KT) { issue_tile(kt + 1, s ^ 1); cp_wait<1>(); }
        else             { cp_wait<0>(); }
        __syncthreads();

        const uint32_t* sA = (const uint32_t*)(sm + s * STAGE);
        const uint32_t* sB = sA + BM * LDS;

        #pragma unroll
        for (int ks = 0; ks < BK / 8; ++ks) {
            uint32_t a[MT][4], b[NT][2];
            #pragma unroll
            for (int mt = 0; mt < MT; ++mt) {
                int r0 = wm0 + mt * 16 + g;
                a[mt][0] = sA[ r0      * LDS + ks * 8 + tig    ];
                a[mt][1] = sA[(r0 + 8) * LDS + ks * 8 + tig    ];
                a[mt][2] = sA[ r0      * LDS + ks * 8 + tig + 4];
                a[mt][3] = sA[(r0 + 8) * LDS + ks * 8 + tig + 4];
            }
            #pragma unroll
            for (int nt = 0; nt < NT; ++nt) {
                int n0 = wn0 + nt * 8 + g;
                b[nt][0] = sB[n0 * LDS + ks * 8 + tig    ];
                b[nt][1] = sB[n0 * LDS + ks * 8 + tig + 4];
            }
            #pragma unroll
            for (int mt = 0; mt < MT; ++mt)
                #pragma unroll
                for (int nt = 0; nt < NT; ++nt)
                    mma_tf32_16x8x8(c[mt][nt], a[mt], b[nt]);
        }
        __syncthreads();
    }

    #pragma unroll
    for (int mt = 0; mt < MT; ++mt) {
        #pragma unroll
        for (int nt = 0; nt < NT; ++nt) {
            int col = nBase + wn0 + nt * 8 + 2 * tig;
            float b0 = bias[col], b1 = bias[col + 1];
            int row0 = mBase + wm0 + mt * 16 + g;
            int row1 = row0 + 8;
            float v0 = c[mt][nt][0] + b0, v1 = c[mt][nt][1] + b1;
            float v2 = c[mt][nt][2] + b0, v3 = c[mt][nt][3] + b1;
            if (RELU) {
                v0 = fmaxf(v0, 0.f); v1 = fmaxf(v1, 0.f);
                v2 = fmaxf(v2, 0.f); v3 = fmaxf(v3, 0.f);
            }
            if (CVT_OUT) {
                v0 = __uint_as_float(f2tf32(v0)); v1 = __uint_as_float(f2tf32(v1));
                v2 = __uint_as_float(f2tf32(v2)); v3 = __uint_as_float(f2tf32(v3));
            }
            if (row0 < Mrows) *(float2*)(C + (size_t)row0 * Ncols + col) = make_float2(v0, v1);
            if (row1 < Mrows) *(float2*)(C + (size_t)row1 * Ncols + col) = make_float2(v2, v3);
        }
    }
}

// k_gemm_proj2: two projections in one launch (layer 2); outputs fp32 accum.
// NTH threads, warps WM x WN; BM=64/NTH=128 -> 628 CTAs (full SM coverage).
template <int BM, int BN, int NTH, int WARPS_M, int WARPS_N>
__global__ __launch_bounds__(NTH) void k_gemm_proj2(
    const float* __restrict__ A, int K,
    const float* __restrict__ Bl, const float* __restrict__ Br,
    float* __restrict__ C1, float* __restrict__ C2,
    int Mrows, int Ncols)
{
    constexpr int BK = 32;
    constexpr int WTM = BM / WARPS_M;
    constexpr int WTN = BN / WARPS_N;
    constexpr int MT = WTM / 16;
    constexpr int NT = WTN / 8;
    constexpr int LDS = BK + 4;
    constexpr int APT = (BM * BK / 4) / NTH;
    constexpr int BPT = (BN * BK / 4) / NTH;
    constexpr int STAGE = (BM + BN) * LDS;

    extern __shared__ float sm[];
    const uint32_t sm_u32 = (uint32_t)__cvta_generic_to_shared(sm);

    const int tid    = threadIdx.x;
    const int warp   = tid >> 5;
    const int lane   = tid & 31;
    const int g      = lane >> 2;
    const int tig    = lane & 3;
    const int wm0    = (warp / WARPS_N) * WTM;
    const int wn0    = (warp % WARPS_N) * WTN;
    const int mBase  = blockIdx.y * BM;

    const int nbPerProj = Ncols / BN;
    const bool second   = (int)blockIdx.x >= nbPerProj;
    const float* B = second ? Br : Bl;
    float*       C = second ? C2 : C1;
    const int nBase = (second ? blockIdx.x - nbPerProj : blockIdx.x) * BN;

    const int KT = K / BK;

    float c[MT][NT][4];
    #pragma unroll
    for (int mt = 0; mt < MT; ++mt)
        #pragma unroll
        for (int nt = 0; nt < NT; ++nt)
            #pragma unroll
            for (int i = 0; i < 4; ++i) c[mt][nt][i] = 0.f;

    auto issue_tile = [&](int kt, int s) {
        const uint32_t aBase = sm_u32 + (s * STAGE) * 4;
        const uint32_t bBase = aBase + (BM * LDS) * 4;
        #pragma unroll
        for (int p = 0; p < APT; ++p) {
            int l    = tid + p * NTH;
            int r    = l >> 3;
            int c4   = (l & 7) * 4;
            int grow = mBase + r;
            int ok   = (grow < Mrows);
            const float* srcp = A + (size_t)(ok ? grow : 0) * K + kt * BK + c4;
            cp_async16(aBase + (r * LDS + c4) * 4, srcp, ok ? 16 : 0);
        }
        #pragma unroll
        for (int p = 0; p < BPT; ++p) {
            int l    = tid + p * NTH;
            int r    = l >> 3;
            int c4   = (l & 7) * 4;
            int grow = nBase + r;
            cp_async16(bBase + (r * LDS + c4) * 4, B + (size_t)grow * K + kt * BK + c4, 16);
        }
        cp_commit();
    };

    issue_tile(0, 0);

    #pragma unroll 1
    for (int kt = 0; kt < KT; ++kt) {
        const int s = kt & 1;
        if (kt + 1 < KT) { issue_tile(kt + 1, s ^ 1); cp_wait<1>(); }
        else             { cp_wait<0>(); }
        __syncthreads();

        const uint32_t* sA = (const uint32_t*)(sm + s * STAGE);
        const uint32_t* sB = sA + BM * LDS;

        #pragma unroll
        for (int ks = 0; ks < BK / 8; ++ks) {
            uint32_t a[MT][4], b[NT][2];
            #pragma unroll
            for (int mt = 0; mt < MT; ++mt) {
                int r0 = wm0 + mt * 16 + g;
                a[mt][0] = sA[ r0      * LDS + ks * 8 + tig    ];
                a[mt][1] = sA[(r0 + 8) * LDS + ks * 8 + tig    ];
                a[mt][2] = sA[ r0      * LDS + ks * 8 + tig + 4];
                a[mt][3] = sA[(r0 + 8) * LDS + ks * 8 + tig + 4];
            }
            #pragma unroll
            for (int nt = 0; nt < NT; ++nt) {
                int n0 = wn0 + nt * 8 + g;
                b[nt][0] = sB[n0 * LDS + ks * 8 + tig    ];
                b[nt][1] = sB[n0 * LDS + ks * 8 + tig + 4];
            }
            #pragma unroll
            for (int mt = 0; mt < MT; ++mt)
                #pragma unroll
                for (int nt = 0; nt < NT; ++nt)
                    mma_tf32_16x8x8(c[mt][nt], a[mt], b[nt]);
        }
        __syncthreads();
    }

    #pragma unroll
    for (int mt = 0; mt < MT; ++mt) {
        #pragma unroll
        for (int nt = 0; nt < NT; ++nt) {
            int col  = nBase + wn0 + nt * 8 + 2 * tig;
            int row0 = mBase + wm0 + mt * 16 + g;
            int row1 = row0 + 8;
            if (row0 < Mrows) *(float2*)(C + (size_t)row0 * Ncols + col) =
                make_float2(c[mt][nt][0], c[mt][nt][1]);
            if (row1 < Mrows) *(float2*)(C + (size_t)row1 * Ncols + col) =
                make_float2(c[mt][nt][2], c[mt][nt][3]);
        }
    }
}

// ---------------- combine + log_softmax (one block of 256 per node) ----------
__global__ __launch_bounds__(256) void k_combine_lsm(
    const float* __restrict__ pl, const float* __restrict__ pr,
    const float* __restrict__ bias, float* __restrict__ out)
{
    __shared__ float redmax[8];
    __shared__ float redsum[8];

    const int node = blockIdx.x;
    const int tid  = threadIdx.x;
    const int wid  = tid >> 5;
    const int lane = tid & 31;

    const int beg = g_off[node], end = g_off[node + 1];
    const float inv = (end > beg) ? 1.0f / (float)(end - beg) : 0.0f;

    float s = 0.f;
    for (int e = beg; e < end; ++e)
        s += pl[(size_t)g_srcs[e] * OUT_DIM + tid];

    float v = s * inv + pr[(size_t)node * OUT_DIM + tid] + bias[tid];

    float m = v;
    #pragma unroll
    for (int o = 16; o > 0; o >>= 1) m = fmaxf(m, __shfl_xor_sync(0xFFFFFFFF, m, o));
    if (lane == 0) redmax[wid] = m;
    __syncthreads();
    float M = redmax[0];
    #pragma unroll
    for (int i = 1; i < 8; ++i) M = fmaxf(M, redmax[i]);

    float e = expf(v - M);
    float t = e;
    #pragma unroll
    for (int o = 16; o > 0; o >>= 1) t += __shfl_xor_sync(0xFFFFFFFF, t, o);
    if (lane == 0) redsum[wid] = t;
    __syncthreads();
    float S = 0.f;
    #pragma unroll
    for (int i = 0; i < 8; ++i) S += redsum[i];

    out[(size_t)node * OUT_DIM + tid] = v - M - logf(S);
}

// ---------------- launch -----------------------------------------------------
extern "C" void kernel_launch(void* const* d_in, const int* in_sizes, int n_in,
                              void* d_out, int out_size) {
    const float* x    = (const float*)d_in[0];
    const int*   ei   = (const int*)d_in[1];
    const float* W1_l = (const float*)d_in[2];
    const float* b1_l = (const float*)d_in[3];
    const float* W1_r = (const float*)d_in[4];
    const float* W2_l = (const float*)d_in[5];
    const float* b2_l = (const float*)d_in[6];
    const float* W2_r = (const float*)d_in[7];
    float* out = (float*)d_out;

    const int* src = ei;            // edge_index[0]
    const int* dst = ei + N_EDGES;  // edge_index[1]

    float *mean1, *xt, *h, *pl, *pr, *w1l, *w1r, *w2l, *w2r;
    cudaGetSymbolAddress((void**)&mean1, g_mean1);
    cudaGetSymbolAddress((void**)&xt,    g_xt);
    cudaGetSymbolAddress((void**)&h,     g_h);
    cudaGetSymbolAddress((void**)&pl,    g_pl);
    cudaGetSymbolAddress((void**)&pr,    g_pr);
    cudaGetSymbolAddress((void**)&w1l,   g_w1l);
    cudaGetSymbolAddress((void**)&w1r,   g_w1r);
    cudaGetSymbolAddress((void**)&w2l,   g_w2l);
    cudaGetSymbolAddress((void**)&w2r,   g_w2r);

    const int smem1 = 2 * (128 + 128) * 36 * 4;   // 73728 B
    const int smem2 = 2 * (64 + 128) * 36 * 4;    // 55296 B
    cudaFuncSetAttribute(k_gemm_dual<128, 128, true, true>,
                         cudaFuncAttributeMaxDynamicSharedMemorySize, smem1);
    cudaFuncSetAttribute(k_gemm_proj2<64, 128, 128, 2, 2>,
                         cudaFuncAttributeMaxDynamicSharedMemorySize, smem2);

    // pre-round weights and x to tf32 bit patterns (one-time streaming pass)
    {
        const int T = 256;
        auto n4 = [](size_t n) { return (int)(n / 4); };
        k_cvt_tf32<<<(n4((size_t)HID * IN_DIM) + T - 1) / T, T>>>(W1_l, w1l, n4((size_t)HID * IN_DIM));
        k_cvt_tf32<<<(n4((size_t)HID * IN_DIM) + T - 1) / T, T>>>(W1_r, w1r, n4((size_t)HID * IN_DIM));
        k_cvt_tf32<<<(n4((size_t)OUT_DIM * HID) + T - 1) / T, T>>>(W2_l, w2l, n4((size_t)OUT_DIM * HID));
        k_cvt_tf32<<<(n4((size_t)OUT_DIM * HID) + T - 1) / T, T>>>(W2_r, w2r, n4((size_t)OUT_DIM * HID));
        k_cvt_tf32<<<(n4((size_t)N_NODES * IN_DIM) + T - 1) / T, T>>>(x, xt, n4((size_t)N_NODES * IN_DIM));
    }

    // CSR build (by dst)
    k_zero <<<(N_NODES + 255) / 256, 256>>>();
    k_count<<<(N_EDGES + 255) / 256, 256>>>(dst);
    k_scan <<<1, 1024>>>();
    k_fill <<<(N_EDGES + 255) / 256, 256>>>(src, dst);
    k_sort <<<(N_NODES + 127) / 128, 128>>>();

    // layer 1: mean-aggregate x (tf32-rounded out), fused dual GEMM -> h (relu, tf32-rounded)
    k_agg_mean<IN_DIM, 1><<<N_NODES, 256>>>(x, mean1);
    k_gemm_dual<128, 128, true, true><<<dim3(HID / 128, (N_NODES + 127) / 128), 256, smem1>>>(
        mean1, w1l, IN_DIM, xt, w1r, IN_DIM, b1_l, h, N_NODES, HID);

    // layer 2: project h to both 256-dim outputs in one launch (BM=64 for
    // full-chip coverage: 4 x 157 = 628 CTAs), then fused combine+log_softmax.
    k_gemm_proj2<64, 128, 128, 2, 2><<<dim3(2 * OUT_DIM / 128, (N_NODES + 63) / 64), 128, smem2>>>(
        h, HID, w2l, w2r, pl, pr, N_NODES, OUT_DIM);

    k_combine_lsm<<<N_NODES, 256>>>(pl, pr, b2_l, out);
}

// round 9
// speedup vs baseline: 3.4963x; 3.4963x over previous
#include <cuda_runtime.h>
#include <cuda_fp16.h>
#include <cstdint>

#define N_NODES 10000
#define N_EDGES 80000
#define IN_DIM  1024
#define HID     4096
#define OUT_DIM 256

// ---------------- scratch (device globals; no allocations allowed) ----------
__device__ int    g_deg[N_NODES];
__device__ int    g_pos[N_NODES];
__device__ int    g_off[N_NODES + 1];
__device__ int    g_srcs[N_EDGES];
__device__ __half g_mean1[(size_t)N_NODES * IN_DIM];    // 20 MB (fp16)
__device__ __half g_xt[(size_t)N_NODES * IN_DIM];       // 20 MB (fp16 x)
__device__ __half g_h[(size_t)N_NODES * HID];           // 80 MB (fp16)
__device__ float  g_pl[(size_t)N_NODES * OUT_DIM];      // 10 MB
__device__ float  g_pr[(size_t)N_NODES * OUT_DIM];      // 10 MB
__device__ __half g_w1l[(size_t)HID * IN_DIM];          // 8 MB
__device__ __half g_w1r[(size_t)HID * IN_DIM];          // 8 MB
__device__ __half g_w2l[(size_t)OUT_DIM * HID];         // 2 MB
__device__ __half g_w2r[(size_t)OUT_DIM * HID];         // 2 MB

// ---------------- helpers ----------------------------------------------------
__device__ __forceinline__ void mma_f16_16x8x16(float* c, const uint32_t* a, const uint32_t* b) {
    asm volatile(
        "mma.sync.aligned.m16n8k16.row.col.f32.f16.f16.f32 "
        "{%0,%1,%2,%3},{%4,%5,%6,%7},{%8,%9},{%0,%1,%2,%3};"
        : "+f"(c[0]), "+f"(c[1]), "+f"(c[2]), "+f"(c[3])
        : "r"(a[0]), "r"(a[1]), "r"(a[2]), "r"(a[3]), "r"(b[0]), "r"(b[1]));
}

__device__ __forceinline__ void ldmatrix_x4(uint32_t& r0, uint32_t& r1, uint32_t& r2, uint32_t& r3,
                                            uint32_t addr) {
    asm volatile("ldmatrix.sync.aligned.m8n8.x4.shared.b16 {%0,%1,%2,%3}, [%4];"
                 : "=r"(r0), "=r"(r1), "=r"(r2), "=r"(r3) : "r"(addr));
}

__device__ __forceinline__ void cp_async16(uint32_t smem_addr, const void* gptr, int src_bytes) {
    asm volatile("cp.async.cg.shared.global [%0], [%1], 16, %2;\n"
                 :: "r"(smem_addr), "l"(gptr), "r"(src_bytes));
}
__device__ __forceinline__ void cp_commit() {
    asm volatile("cp.async.commit_group;\n" ::: "memory");
}
template <int N>
__device__ __forceinline__ void cp_wait() {
    asm volatile("cp.async.wait_group %0;\n" :: "n"(N) : "memory");
}

// ---------------- fused fp32->fp16 conversion + counter zeroing --------------
#define N4_W1 (HID * IN_DIM / 4)        // 1048576
#define N4_W2 (OUT_DIM * HID / 4)       // 262144
#define N4_X  (N_NODES * IN_DIM / 4)    // 2560000
#define N4_TOTAL (2 * N4_W1 + 2 * N4_W2 + N4_X)

__device__ __forceinline__ void cvt4(const float* __restrict__ src, __half* __restrict__ dst, int j) {
    float4 v = ((const float4*)src)[j];
    ((__half2*)dst)[2 * j]     = __floats2half2_rn(v.x, v.y);
    ((__half2*)dst)[2 * j + 1] = __floats2half2_rn(v.z, v.w);
}

__global__ void k_cvt_zero(
    const float* __restrict__ x,
    const float* __restrict__ W1_l, const float* __restrict__ W1_r,
    const float* __restrict__ W2_l, const float* __restrict__ W2_r,
    __half* __restrict__ xt,
    __half* __restrict__ w1l, __half* __restrict__ w1r,
    __half* __restrict__ w2l, __half* __restrict__ w2r)
{
    int i = blockIdx.x * blockDim.x + threadIdx.x;
    if (i < N_NODES) { g_deg[i] = 0; g_pos[i] = 0; }
    if (i < N4_W1)                         cvt4(W1_l, w1l, i);
    else if (i < 2 * N4_W1)                cvt4(W1_r, w1r, i - N4_W1);
    else if (i < 2 * N4_W1 + N4_W2)        cvt4(W2_l, w2l, i - 2 * N4_W1);
    else if (i < 2 * N4_W1 + 2 * N4_W2)    cvt4(W2_r, w2r, i - 2 * N4_W1 - N4_W2);
    else if (i < N4_TOTAL)                 cvt4(x, xt, i - 2 * N4_W1 - 2 * N4_W2);
}

// ---------------- CSR build --------------------------------------------------
__global__ void k_count(const int* __restrict__ dst) {
    int e = blockIdx.x * blockDim.x + threadIdx.x;
    if (e < N_EDGES) atomicAdd(&g_deg[dst[e]], 1);
}

__global__ void k_scan() {
    __shared__ int s[1024];
    int tid = threadIdx.x;
    int carry = 0;
    if (tid == 0) g_off[0] = 0;
    for (int base = 0; base < N_NODES; base += 1024) {
        int i = base + tid;
        int v = (i < N_NODES) ? g_deg[i] : 0;
        s[tid] = v;
        __syncthreads();
        #pragma unroll
        for (int off = 1; off < 1024; off <<= 1) {
            int t = (tid >= off) ? s[tid - off] : 0;
            __syncthreads();
            s[tid] += t;
            __syncthreads();
        }
        if (i < N_NODES) g_off[i + 1] = carry + s[tid];
        carry += s[1023];
        __syncthreads();
    }
}

__global__ void k_fill(const int* __restrict__ src, const int* __restrict__ dst) {
    int e = blockIdx.x * blockDim.x + threadIdx.x;
    if (e < N_EDGES) {
        int d = dst[e];
        int p = atomicAdd(&g_pos[d], 1);
        g_srcs[g_off[d] + p] = src[e];
    }
}

// ---------------- sort + mean aggregation (one block of 256 per node) --------
// Thread 0 insertion-sorts the node's segment (determinism; sorted order
// persists in g_srcs for the layer-2 combine), then all threads aggregate
// fp16 xt rows with fp32 accumulation, emitting fp16 mean1.
__global__ __launch_bounds__(256) void k_sort_agg(const __half* __restrict__ xt,
                                                  __half* __restrict__ outm) {
    int node = blockIdx.x;
    int beg = g_off[node], end = g_off[node + 1];

    if (threadIdx.x == 0) {
        for (int i = beg + 1; i < end; ++i) {
            int key = g_srcs[i];
            int j = i - 1;
            while (j >= beg && g_srcs[j] > key) { g_srcs[j + 1] = g_srcs[j]; --j; }
            g_srcs[j + 1] = key;
        }
    }
    __syncthreads();

    float inv = (end > beg) ? 1.0f / (float)(end - beg) : 0.0f;
    float a0 = 0.f, a1 = 0.f, a2 = 0.f, a3 = 0.f;
    for (int e = beg; e < end; ++e) {
        int s = g_srcs[e];
        uint2 u = ((const uint2*)(xt + (size_t)s * IN_DIM))[threadIdx.x];
        float2 f0 = __half22float2(*(__half2*)&u.x);
        float2 f1 = __half22float2(*(__half2*)&u.y);
        a0 += f0.x; a1 += f0.y; a2 += f1.x; a3 += f1.y;
    }
    __half2 o0 = __floats2half2_rn(a0 * inv, a1 * inv);
    __half2 o1 = __floats2half2_rn(a2 * inv, a3 * inv);
    uint2 ou;
    ou.x = *(uint32_t*)&o0;
    ou.y = *(uint32_t*)&o1;
    ((uint2*)(outm + (size_t)node * IN_DIM))[threadIdx.x] = ou;
}

// ---------------- dual-source fused GEMM (fp16 mma + ldmatrix) ---------------
// C[M,Ncols] = A1*B1^T + A2*B2^T + bias, relu, fp16 output. 256 thr, warps 4x2.
// smem rows: BK=64 halfs = 32 uint32 data, padded LDS2=36 (144 B rows).
template <int BM, int BN>
__global__ __launch_bounds__(256) void k_gemm_dual(
    const __half* __restrict__ A1, const __half* __restrict__ B1, int K1,
    const __half* __restrict__ A2, const __half* __restrict__ B2, int K2,
    const float* __restrict__ bias, __half* __restrict__ C,
    int Mrows, int Ncols)
{
    constexpr int BK = 64;
    constexpr int WARPS_M = 4, WARPS_N = 2;
    constexpr int WTM = BM / WARPS_M;            // 32
    constexpr int WTN = BN / WARPS_N;            // 64
    constexpr int MT = WTM / 16;                 // 2
    constexpr int NT = WTN / 8;                  // 8
    constexpr int LDS2 = BK / 2 + 4;             // 36 uint32 per row
    constexpr int ROWB = LDS2 * 4;               // 144 B row stride
    constexpr int CPRA = (BM * BK / 8) / 256;
    constexpr int CPRB = (BN * BK / 8) / 256;
    constexpr int STAGE = (BM + BN) * LDS2;

    extern __shared__ uint32_t sm[];
    const uint32_t sm_u32 = (uint32_t)__cvta_generic_to_shared(sm);

    const int tid    = threadIdx.x;
    const int warp   = tid >> 5;
    const int lane   = tid & 31;
    const int g      = lane >> 2;
    const int tig    = lane & 3;
    const int wm0    = (warp / WARPS_N) * WTM;
    const int wn0    = (warp % WARPS_N) * WTN;
    const int mBase  = blockIdx.y * BM;
    const int nBase  = blockIdx.x * BN;

    // ldmatrix per-thread byte offsets (within a stage)
    const uint32_t aOff = (uint32_t)(wm0 + (lane & 15)) * ROWB + (lane >> 4) * 16;
    const uint32_t bOff = (uint32_t)(wn0 + ((lane >> 4) & 1) * 8 + (lane & 7)) * ROWB
                        + ((lane >> 3) & 1) * 16;

    const int KT1 = K1 / BK;
    const int KT  = KT1 + K2 / BK;

    float c[MT][NT][4];
    #pragma unroll
    for (int mt = 0; mt < MT; ++mt)
        #pragma unroll
        for (int nt = 0; nt < NT; ++nt)
            #pragma unroll
            for (int i = 0; i < 4; ++i) c[mt][nt][i] = 0.f;

    auto issue_tile = [&](int kt, int s) {
        const __half* A; const __half* B; int K; int ktp;
        if (kt < KT1) { A = A1; B = B1; K = K1; ktp = kt; }
        else          { A = A2; B = B2; K = K2; ktp = kt - KT1; }
        const uint32_t aBase = sm_u32 + (s * STAGE) * 4;
        const uint32_t bBase = aBase + BM * ROWB;
        #pragma unroll
        for (int p = 0; p < CPRA; ++p) {
            int l    = tid + p * 256;
            int r    = l >> 3;
            int c16  = l & 7;
            int grow = mBase + r;
            int ok   = (grow < Mrows);
            const __half* srcp = A + (size_t)(ok ? grow : 0) * K + ktp * BK + c16 * 8;
            cp_async16(aBase + r * ROWB + c16 * 16, srcp, ok ? 16 : 0);
        }
        #pragma unroll
        for (int p = 0; p < CPRB; ++p) {
            int l    = tid + p * 256;
            int r    = l >> 3;
            int c16  = l & 7;
            int grow = nBase + r;
            cp_async16(bBase + r * ROWB + c16 * 16,
                       B + (size_t)grow * K + ktp * BK + c16 * 8, 16);
        }
        cp_commit();
    };

    issue_tile(0, 0);

    #pragma unroll 1
    for (int kt = 0; kt < KT; ++kt) {
        const int s = kt & 1;
        if (kt + 1 < KT) { issue_tile(kt + 1, s ^ 1); cp_wait<1>(); }
        else             { cp_wait<0>(); }
        __syncthreads();

        const uint32_t aBase = sm_u32 + (s * STAGE) * 4 + aOff;
        const uint32_t bBase = sm_u32 + (s * STAGE) * 4 + BM * ROWB + bOff;

        #pragma unroll
        for (int ks = 0; ks < BK / 16; ++ks) {
            uint32_t a[MT][4], b[NT][2];
            #pragma unroll
            for (int mt = 0; mt < MT; ++mt)
                ldmatrix_x4(a[mt][0], a[mt][1], a[mt][2], a[mt][3],
                            aBase + mt * 16 * ROWB + ks * 32);
            #pragma unroll
            for (int nt2 = 0; nt2 < NT / 2; ++nt2)
                ldmatrix_x4(b[2 * nt2][0], b[2 * nt2][1], b[2 * nt2 + 1][0], b[2 * nt2 + 1][1],
                            bBase + nt2 * 16 * ROWB + ks * 32);
            #pragma unroll
            for (int mt = 0; mt < MT; ++mt)
                #pragma unroll
                for (int nt = 0; nt < NT; ++nt)
                    mma_f16_16x8x16(c[mt][nt], a[mt], b[nt]);
        }
        __syncthreads();
    }

    // epilogue: +bias, relu, fp16 half2 stores
    #pragma unroll
    for (int mt = 0; mt < MT; ++mt) {
        #pragma unroll
        for (int nt = 0; nt < NT; ++nt) {
            int col = nBase + wn0 + nt * 8 + 2 * tig;
            float b0 = bias[col], b1 = bias[col + 1];
            int row0 = mBase + wm0 + mt * 16 + g;
            int row1 = row0 + 8;
            float v0 = fmaxf(c[mt][nt][0] + b0, 0.f);
            float v1 = fmaxf(c[mt][nt][1] + b1, 0.f);
            float v2 = fmaxf(c[mt][nt][2] + b0, 0.f);
            float v3 = fmaxf(c[mt][nt][3] + b1, 0.f);
            if (row0 < Mrows)
                *(__half2*)(C + (size_t)row0 * Ncols + col) = __floats2half2_rn(v0, v1);
            if (row1 < Mrows)
                *(__half2*)(C + (size_t)row1 * Ncols + col) = __floats2half2_rn(v2, v3);
        }
    }
}

// ---------------- dual projection GEMM (layer 2, fp16 in / fp32 out) ---------
// BM=64, 128 threads (2x2 warps) -> 628 CTAs for full-chip coverage.
template <int BM, int BN, int NTH, int WARPS_M, int WARPS_N>
__global__ __launch_bounds__(NTH) void k_gemm_proj2(
    const __half* __restrict__ A, int K,
    const __half* __restrict__ Bl, const __half* __restrict__ Br,
    float* __restrict__ C1, float* __restrict__ C2,
    int Mrows, int Ncols)
{
    constexpr int BK = 64;
    constexpr int WTM = BM / WARPS_M;
    constexpr int WTN = BN / WARPS_N;
    constexpr int MT = WTM / 16;
    constexpr int NT = WTN / 8;
    constexpr int LDS2 = BK / 2 + 4;
    constexpr int ROWB = LDS2 * 4;
    constexpr int CPRA = (BM * BK / 8) / NTH;
    constexpr int CPRB = (BN * BK / 8) / NTH;
    constexpr int STAGE = (BM + BN) * LDS2;

    extern __shared__ uint32_t sm[];
    const uint32_t sm_u32 = (uint32_t)__cvta_generic_to_shared(sm);

    const int tid    = threadIdx.x;
    const int warp   = tid >> 5;
    const int lane   = tid & 31;
    const int g      = lane >> 2;
    const int tig    = lane & 3;
    const int wm0    = (warp / WARPS_N) * WTM;
    const int wn0    = (warp % WARPS_N) * WTN;
    const int mBase  = blockIdx.y * BM;

    const uint32_t aOff = (uint32_t)(wm0 + (lane & 15)) * ROWB + (lane >> 4) * 16;
    const uint32_t bOff = (uint32_t)(wn0 + ((lane >> 4) & 1) * 8 + (lane & 7)) * ROWB
                        + ((lane >> 3) & 1) * 16;

    const int nbPerProj = Ncols / BN;
    const bool second   = (int)blockIdx.x >= nbPerProj;
    const __half* B = second ? Br : Bl;
    float*        C = second ? C2 : C1;
    const int nBase = (second ? blockIdx.x - nbPerProj : blockIdx.x) * BN;

    const int KT = K / BK;

    float c[MT][NT][4];
    #pragma unroll
    for (int mt = 0; mt < MT; ++mt)
        #pragma unroll
        for (int nt = 0; nt < NT; ++nt)
            #pragma unroll
            for (int i = 0; i < 4; ++i) c[mt][nt][i] = 0.f;

    auto issue_tile = [&](int kt, int s) {
        const uint32_t aBase = sm_u32 + (s * STAGE) * 4;
        const uint32_t bBase = aBase + BM * ROWB;
        #pragma unroll
        for (int p = 0; p < CPRA; ++p) {
            int l    = tid + p * NTH;
            int r    = l >> 3;
            int c16  = l & 7;
            int grow = mBase + r;
            int ok   = (grow < Mrows);
            const __half* srcp = A + (size_t)(ok ? grow : 0) * K + kt * BK + c16 * 8;
            cp_async16(aBase + r * ROWB + c16 * 16, srcp, ok ? 16 : 0);
        }
        #pragma unroll
        for (int p = 0; p < CPRB; ++p) {
            int l    = tid + p * NTH;
            int r    = l >> 3;
            int c16  = l & 7;
            int grow = nBase + r;
            cp_async16(bBase + r * ROWB + c16 * 16,
                       B + (size_t)grow * K + kt * BK + c16 * 8, 16);
        }
        cp_commit();
    };

    issue_tile(0, 0);

    #pragma unroll 1
    for (int kt = 0; kt < KT; ++kt) {
        const int s = kt & 1;
        if (kt + 1 < KT) { issue_tile(kt + 1, s ^ 1); cp_wait<1>(); }
        else             { cp_wait<0>(); }
        __syncthreads();

        const uint32_t aBase = sm_u32 + (s * STAGE) * 4 + aOff;
        const uint32_t bBase = sm_u32 + (s * STAGE) * 4 + BM * ROWB + bOff;

        #pragma unroll
        for (int ks = 0; ks < BK / 16; ++ks) {
            uint32_t a[MT][4], b[NT][2];
            #pragma unroll
            for (int mt = 0; mt < MT; ++mt)
                ldmatrix_x4(a[mt][0], a[mt][1], a[mt][2], a[mt][3],
                            aBase + mt * 16 * ROWB + ks * 32);
            #pragma unroll
            for (int nt2 = 0; nt2 < NT / 2; ++nt2)
                ldmatrix_x4(b[2 * nt2][0], b[2 * nt2][1], b[2 * nt2 + 1][0], b[2 * nt2 + 1][1],
                            bBase + nt2 * 16 * ROWB + ks * 32);
            #pragma unroll
            for (int mt = 0; mt < MT; ++mt)
                #pragma unroll
                for (int nt = 0; nt < NT; ++nt)
                    mma_f16_16x8x16(c[mt][nt], a[mt], b[nt]);
        }
        __syncthreads();
    }

    #pragma unroll
    for (int mt = 0; mt < MT; ++mt) {
        #pragma unroll
        for (int nt = 0; nt < NT; ++nt) {
            int col  = nBase + wn0 + nt * 8 + 2 * tig;
            int row0 = mBase + wm0 + mt * 16 + g;
            int row1 = row0 + 8;
            if (row0 < Mrows) *(float2*)(C + (size_t)row0 * Ncols + col) =
                make_float2(c[mt][nt][0], c[mt][nt][1]);
            if (row1 < Mrows) *(float2*)(C + (size_t)row1 * Ncols + col) =
                make_float2(c[mt][nt][2], c[mt][nt][3]);
        }
    }
}

// ---------------- combine + log_softmax (one block of 256 per node) ----------
__global__ __launch_bounds__(256) void k_combine_lsm(
    const float* __restrict__ pl, const float* __restrict__ pr,
    const float* __restrict__ bias, float* __restrict__ out)
{
    __shared__ float redmax[8];
    __shared__ float redsum[8];

    const int node = blockIdx.x;
    const int tid  = threadIdx.x;
    const int wid  = tid >> 5;
    const int lane = tid & 31;

    const int beg = g_off[node], end = g_off[node + 1];
    const float inv = (end > beg) ? 1.0f / (float)(end - beg) : 0.0f;

    float s = 0.f;
    for (int e = beg; e < end; ++e)
        s += pl[(size_t)g_srcs[e] * OUT_DIM + tid];

    float v = s * inv + pr[(size_t)node * OUT_DIM + tid] + bias[tid];

    float m = v;
    #pragma unroll
    for (int o = 16; o > 0; o >>= 1) m = fmaxf(m, __shfl_xor_sync(0xFFFFFFFF, m, o));
    if (lane == 0) redmax[wid] = m;
    __syncthreads();
    float M = redmax[0];
    #pragma unroll
    for (int i = 1; i < 8; ++i) M = fmaxf(M, redmax[i]);

    float e = expf(v - M);
    float t = e;
    #pragma unroll
    for (int o = 16; o > 0; o >>= 1) t += __shfl_xor_sync(0xFFFFFFFF, t, o);
    if (lane == 0) redsum[wid] = t;
    __syncthreads();
    float S = 0.f;
    #pragma unroll
    for (int i = 0; i < 8; ++i) S += redsum[i];

    out[(size_t)node * OUT_DIM + tid] = v - M - logf(S);
}

// ---------------- launch -----------------------------------------------------
extern "C" void kernel_launch(void* const* d_in, const int* in_sizes, int n_in,
                              void* d_out, int out_size) {
    const float* x    = (const float*)d_in[0];
    const int*   ei   = (const int*)d_in[1];
    const float* W1_l = (const float*)d_in[2];
    const float* b1_l = (const float*)d_in[3];
    const float* W1_r = (const float*)d_in[4];
    const float* W2_l = (const float*)d_in[5];
    const float* b2_l = (const float*)d_in[6];
    const float* W2_r = (const float*)d_in[7];
    float* out = (float*)d_out;

    const int* src = ei;            // edge_index[0]
    const int* dst = ei + N_EDGES;  // edge_index[1]

    __half *mean1, *xt, *h, *w1l, *w1r, *w2l, *w2r;
    float *pl, *pr;
    cudaGetSymbolAddress((void**)&mean1, g_mean1);
    cudaGetSymbolAddress((void**)&xt,    g_xt);
    cudaGetSymbolAddress((void**)&h,     g_h);
    cudaGetSymbolAddress((void**)&pl,    g_pl);
    cudaGetSymbolAddress((void**)&pr,    g_pr);
    cudaGetSymbolAddress((void**)&w1l,   g_w1l);
    cudaGetSymbolAddress((void**)&w1r,   g_w1r);
    cudaGetSymbolAddress((void**)&w2l,   g_w2l);
    cudaGetSymbolAddress((void**)&w2r,   g_w2r);

    const int smem1 = 2 * (128 + 128) * 36 * 4;   // 73728 B
    const int smem2 = 2 * (64 + 128) * 36 * 4;    // 55296 B
    cudaFuncSetAttribute(k_gemm_dual<128, 128>,
                         cudaFuncAttributeMaxDynamicSharedMemorySize, smem1);
    cudaFuncSetAttribute(k_gemm_proj2<64, 128, 128, 2, 2>,
                         cudaFuncAttributeMaxDynamicSharedMemorySize, smem2);

    // 0: fused fp32->fp16 conversion (weights + x) + zero CSR counters
    k_cvt_zero<<<(N4_TOTAL + 255) / 256, 256>>>(x, W1_l, W1_r, W2_l, W2_r,
                                                xt, w1l, w1r, w2l, w2r);
    // 1-3: CSR build
    k_count<<<(N_EDGES + 255) / 256, 256>>>(dst);
    k_scan <<<1, 1024>>>();
    k_fill <<<(N_EDGES + 255) / 256, 256>>>(src, dst);
    // 4: per-segment sort fused with layer-1 mean aggregation (reads fp16 xt)
    k_sort_agg<<<N_NODES, 256>>>(xt, mean1);

    // 5 (ncu -s 5 -c 1 profiles this): layer-1 fused dual GEMM -> h
    k_gemm_dual<128, 128><<<dim3(HID / 128, (N_NODES + 127) / 128), 256, smem1>>>(
        mean1, w1l, IN_DIM, xt, w1r, IN_DIM, b1_l, h, N_NODES, HID);

    // 6: layer-2 both projections in one launch
    k_gemm_proj2<64, 128, 128, 2, 2><<<dim3(2 * OUT_DIM / 128, (N_NODES + 63) / 64), 128, smem2>>>(
        h, HID, w2l, w2r, pl, pr, N_NODES, OUT_DIM);

    // 7: fused combine + log_softmax
    k_combine_lsm<<<N_NODES, 256>>>(pl, pr, b2_l, out);
}